// round 13
// baseline (speedup 1.0000x reference)
#include <cuda_runtime.h>
#include <cuda_fp16.h>

typedef unsigned long long ull;

constexpr int cN = 256, cC = 64, cT = 128, cV = 25, cO = 64;
constexpr int TV  = cT * cV;          // 3200 contiguous (t,v) per (n, channel)

// scratch (no allocations allowed)
__device__ float   g_xsum[cN * cC * cV];                    // 1.6 MB
__device__ float   g_att[(size_t)cN * cO * cV * cV];        // 41 MB
__device__ __half2 g_vtenh[(size_t)cN * cO * TV / 2];       // 105 MB

__device__ __forceinline__ float2 u2f(ull v) {
    float2 r;
    asm("mov.b64 {%0, %1}, %2;" : "=f"(r.x), "=f"(r.y) : "l"(v));
    return r;
}

// ---------------------------------------------------------------------------
// K1: xsum[n,c,v] = sum_t x[n,c,t,v]   (HBM-roof bound, ~40us, keep)
// ---------------------------------------------------------------------------
__global__ void k_sum_t(const float* __restrict__ x) {
    int n = blockIdx.y;
    int c = blockIdx.x * 8 + (threadIdx.x >> 5);
    int lane = threadIdx.x & 31;
    if (lane < cV) {
        const float* p = x + ((size_t)(n * cC + c) * cT) * cV + lane;
        float s = 0.f;
        #pragma unroll 8
        for (int t = 0; t < cT; ++t) s += p[t * cV];
        g_xsum[(n * cC + c) * cV + lane] = s;
    }
}

// ---------------------------------------------------------------------------
// K2: attention matrix (keep)
// ---------------------------------------------------------------------------
__global__ void __launch_bounds__(256) k_att_kernel(
    const float* __restrict__ adj,
    const float* __restrict__ Wk, const float* __restrict__ bk,
    const float* __restrict__ Wq, const float* __restrict__ bq,
    const float* __restrict__ c1w, const float* __restrict__ c1b,
    const float* __restrict__ c2w, const float* __restrict__ c2b,
    const float* __restrict__ fw,  const float* __restrict__ fb,
    const float* __restrict__ alpha) {
    __shared__ float xs2[cC * cV];
    __shared__ float ksh[4 * cV], qsh[4 * cV];
    __shared__ float fwal[cO * 8];              // alpha * fw
    __shared__ float adjsh[cV * cV];
    __shared__ float aa[625 * 9];               // tanh features, stride 9
    __shared__ float c1sh[16], c2sh[16], c1bs[4], c2bs[4], fbal[cO], bks[4], bqs[4];

    int n = blockIdx.y, oh = blockIdx.x, tid = threadIdx.x;
    float al = alpha[0];
    for (int i = tid; i < cC * cV; i += 256) xs2[i] = g_xsum[n * cC * cV + i];
    for (int i = tid; i < cO * 8; i += 256)  fwal[i] = al * fw[i];
    for (int i = tid; i < cV * cV; i += 256) adjsh[i] = adj[i];
    if (tid < 16) { c1sh[tid] = c1w[tid]; c2sh[tid] = c2w[tid]; }
    if (tid < 4)  { c1bs[tid] = c1b[tid]; c2bs[tid] = c2b[tid]; bks[tid] = bk[tid]; bqs[tid] = bq[tid]; }
    if (tid < cO) fbal[tid] = al * fb[tid];
    __syncthreads();

    if (tid < 100) {
        int r = tid / cV, v = tid % cV;
        float a = 0.f;
        for (int c = 0; c < cC; ++c) a += Wk[r * cC + c] * xs2[c * cV + v];
        ksh[tid] = a * (1.f / cT) + bks[r];
    } else if (tid < 200) {
        int j = tid - 100;
        int r = j / cV, v = j % cV;
        float a = 0.f;
        for (int c = 0; c < cC; ++c) a += Wq[r * cC + c] * xs2[c * cV + v];
        qsh[j] = a * (1.f / cT) + bqs[r];
    }
    __syncthreads();

    for (int p = tid; p < 625; p += 256) {
        int v = p / cV, u = p - v * cV;
        float kv[4], qu[4];
        #pragma unroll
        for (int r = 0; r < 4; ++r) { kv[r] = ksh[r * cV + v]; qu[r] = qsh[r * cV + u]; }
        #pragma unroll
        for (int s = 0; s < 4; ++s) {
            float s1 = c1bs[s], s2 = c2bs[s];
            #pragma unroll
            for (int r = 0; r < 4; ++r) {
                s1 += c1sh[s * 4 + r] * (kv[r] * qu[r]);
                s2 += c2sh[s * 4 + r] * (kv[r] - qu[r]);
            }
            aa[p * 9 + s]     = tanhf(s1);
            aa[p * 9 + 4 + s] = tanhf(s2);
        }
    }
    __syncthreads();

    int o0 = oh * 32;
    for (int o = o0; o < o0 + 32; ++o) {
        float w0 = fwal[o*8+0], w1 = fwal[o*8+1], w2 = fwal[o*8+2], w3 = fwal[o*8+3];
        float w4 = fwal[o*8+4], w5 = fwal[o*8+5], w6 = fwal[o*8+6], w7 = fwal[o*8+7];
        float fb_ = fbal[o];
        float* dst = g_att + (size_t)(n * cO + o) * 625;
        for (int p = tid; p < 625; p += 256) {
            const float* a = aa + p * 9;
            float acc = fb_ + adjsh[p];
            acc += w0 * a[0]; acc += w1 * a[1]; acc += w2 * a[2]; acc += w3 * a[3];
            acc += w4 * a[4]; acc += w5 * a[5]; acc += w6 * a[6]; acc += w7 * a[7];
            dst[p] = acc;
        }
    }
}

// ---------------------------------------------------------------------------
// K3: vten[n,o,i] = sum_c Wv[o,c] * x[n,c,i] + bv[o]  -> fp16 store
// i-paired f32x2: Wv staged pre-duplicated (wdup[o][c]=(w,w)), x float4
// reinterpreted as 2 ull for free -> ZERO packing movs in the mainloop.
// Thread tile 8 o x 8 i. Per c: 2 LDS.128 (x, conflict-free) +
// 8 broadcast LDS.64 (w) + 32 FFMA2. smem 64KB -> 3 blocks/SM.
// ---------------------------------------------------------------------------
constexpr int CH = 128;  // i-chunk

__global__ void __launch_bounds__(128, 3) k_vten(
    const float* __restrict__ x, const float* __restrict__ Wv,
    const float* __restrict__ bv) {
    __shared__ __align__(16) float xs[cC * CH];   // 32 KB
    __shared__ __align__(16) ull   wdup[cO * cC]; // 32 KB

    int n  = blockIdx.y;
    int i0c = blockIdx.x * CH;
    int tid = threadIdx.x;

    for (int i = tid; i < cC * (CH / 4); i += 128) {
        int c = i >> 5, j = i & 31;
        ((float4*)xs)[i] =
            ((const float4*)(x + (size_t)(n * cC + c) * TV + i0c))[j];
    }
    for (int i = tid; i < cO * cC; i += 128) {
        float w = Wv[i];
        ((float2*)wdup)[i] = make_float2(w, w);
    }
    __syncthreads();

    int osub = tid >> 4;          // 0..7 -> o = osub*8 + oo
    int tug  = tid & 15;
    int i0   = tug * 4;           // floats; second group at +64
    const ull* wbase = wdup + (osub * 8) * cC;

    ull acc[8][4];                // [oo][j]: j<2 -> i0+2j, j>=2 -> i0+64+2(j-2)
    #pragma unroll
    for (int oo = 0; oo < 8; ++oo)
        #pragma unroll
        for (int j = 0; j < 4; ++j) acc[oo][j] = 0ull;

    #pragma unroll 4
    for (int c = 0; c < cC; ++c) {
        float4 xa = *(const float4*)(xs + c * CH + i0);        // conflict-free
        float4 xb = *(const float4*)(xs + c * CH + 64 + i0);   // conflict-free
        ull xd0 = ((const ull*)&xa)[0], xd1 = ((const ull*)&xa)[1];
        ull xd2 = ((const ull*)&xb)[0], xd3 = ((const ull*)&xb)[1];
        #pragma unroll
        for (int oo = 0; oo < 8; ++oo) {
            ull w = wbase[oo * cC + c];                        // broadcast
            asm("fma.rn.f32x2 %0, %1, %2, %0;" : "+l"(acc[oo][0]) : "l"(xd0), "l"(w));
            asm("fma.rn.f32x2 %0, %1, %2, %0;" : "+l"(acc[oo][1]) : "l"(xd1), "l"(w));
            asm("fma.rn.f32x2 %0, %1, %2, %0;" : "+l"(acc[oo][2]) : "l"(xd2), "l"(w));
            asm("fma.rn.f32x2 %0, %1, %2, %0;" : "+l"(acc[oo][3]) : "l"(xd3), "l"(w));
        }
    }

    // epilogue: bias + fp16 pack + coalesced 8B stores
    #pragma unroll
    for (int oo = 0; oo < 8; ++oo) {
        int o = osub * 8 + oo;
        float b = __ldg(bv + o);
        __half2 h[4];
        #pragma unroll
        for (int j = 0; j < 4; ++j) {
            float2 f = u2f(acc[oo][j]);
            h[j] = __floats2half2_rn(f.x + b, f.y + b);
        }
        __half2* row = g_vtenh + ((size_t)(n * cO + o) * TV + i0c) / 2;
        uint2 p0, p1;
        p0.x = *(unsigned*)&h[0]; p0.y = *(unsigned*)&h[1];
        p1.x = *(unsigned*)&h[2]; p1.y = *(unsigned*)&h[3];
        *(uint2*)(row + i0 / 2)        = p0;   // halves i0..i0+3
        *(uint2*)(row + (64 + i0) / 2) = p1;   // halves i0+64..i0+67
    }
}

// ---------------------------------------------------------------------------
// K4: out[n,o,t,v] = sum_u att[n,o,v,u] * vten[n,o,t,u]
// grid (32, N): o-pairs, 320 threads, 3 blocks/SM. Staging reads g_vtenh
// (fp16, linear coalesced, half the LDG traffic), converts to f32 during
// the padded-row scatter. Mainloop unchanged (u-paired f32x2, stride-13
// conflict-free ull rows). Writeback via smem -> linear f32 stores.
// ---------------------------------------------------------------------------
constexpr int RS = 26;   // padded row stride (floats)

__global__ void __launch_bounds__(320, 3) k_out(float* __restrict__ out) {
    __shared__ __align__(16) float vtr[2 * cT * RS];     // 6656 fl; reused as outsh
    __shared__ __align__(16) float ash[2 * cV * RS];     // 1300 fl

    int n  = blockIdx.y;
    int op = blockIdx.x;
    int tid = threadIdx.x;
    int obase = n * cO + op * 2;

    // ---- stage vt: linear coalesced half2 reads, f32 scatter into padded rows
    const __half2* vsrc = g_vtenh + (size_t)obase * (TV / 2);  // 3200 half2
    #pragma unroll
    for (int k = 0; k < 10; ++k) {                             // 10*320 = 3200
        int g = k * 320 + tid;
        float2 d = __half22float2(vsrc[g]);
        int r0 = 2 * g;
        int oiA = (r0 >= TV);
        int rA  = r0 - oiA * TV;
        int tA  = rA / cV, uA = rA - tA * cV;
        vtr[oiA * (cT * RS) + tA * RS + uA] = d.x;
        int r1 = r0 + 1;
        int oiB = (r1 >= TV);
        int rB  = r1 - oiB * TV;
        int tB  = rB / cV, uB = rB - tB * cV;
        vtr[oiB * (cT * RS) + tB * RS + uB] = d.y;
    }
    // ---- stage att: 1250 contiguous floats
    const float* asrc = g_att + (size_t)obase * 625;
    for (int i = tid; i < 1250; i += 320) {
        float d = asrc[i];
        int oi2 = (i >= 625);
        int r  = i - oi2 * 625;
        int v  = r / cV, u = r - v * cV;
        ash[oi2 * (cV * RS) + v * RS + u] = d;
    }
    // ---- zero pad columns (u = 25)
    if (tid < 256) {
        int oi2 = tid >> 7, t = tid & 127;
        vtr[oi2 * (cT * RS) + t * RS + cV] = 0.f;
    } else if (tid < 306) {
        int j = tid - 256;
        int oi2 = (j >= 25) ? 1 : 0;
        int v = j - 25 * oi2;
        ash[oi2 * (cV * RS) + v * RS + cV] = 0.f;
    }
    __syncthreads();

    int w  = tid >> 5;
    int tg = tid & 31;
    int oi = (w >= 5) ? 1 : 0;
    int vq = w - 5 * oi;

    const ull* ab  = (const ull*)(ash + oi * (cV * RS) + (vq * 5) * RS); // +vi*13
    const ull* vbb = (const ull*)(vtr + oi * (cT * RS)) + tg * (RS / 2); // +ti*32*13

    ull acc[5][4];
    #pragma unroll
    for (int vi = 0; vi < 5; ++vi)
        #pragma unroll
        for (int ti = 0; ti < 4; ++ti) acc[vi][ti] = 0ull;

    #pragma unroll
    for (int up = 0; up < 13; ++up) {
        ull a_u[5], v_u[4];
        #pragma unroll
        for (int vi = 0; vi < 5; ++vi) a_u[vi] = ab[vi * 13 + up];         // broadcast
        #pragma unroll
        for (int ti = 0; ti < 4; ++ti) v_u[ti] = vbb[ti * (32 * 13) + up]; // cf
        #pragma unroll
        for (int vi = 0; vi < 5; ++vi)
            #pragma unroll
            for (int ti = 0; ti < 4; ++ti)
                asm("fma.rn.f32x2 %0, %1, %2, %0;"
                    : "+l"(acc[vi][ti]) : "l"(a_u[vi]), "l"(v_u[ti]));
    }
    __syncthreads();   // all reads of vtr done -> reuse as output buffer

    // ---- results into smem (unpadded t*25+v; lane stride 25 -> conflict-free)
    float* outsh = vtr;
    #pragma unroll
    for (int ti = 0; ti < 4; ++ti) {
        int t = ti * 32 + tg;
        #pragma unroll
        for (int vi = 0; vi < 5; ++vi) {
            float2 f = u2f(acc[vi][ti]);
            outsh[oi * TV + t * cV + vq * 5 + vi] = f.x + f.y;
        }
    }
    __syncthreads();

    // ---- linear coalesced writeback
    float* odst = out + (size_t)obase * TV;
    #pragma unroll
    for (int k = 0; k < 20; ++k) {
        int i = k * 320 + tid;
        odst[i] = outsh[i];
    }
}

// ---------------------------------------------------------------------------
extern "C" void kernel_launch(void* const* d_in, const int* in_sizes, int n_in,
                              void* d_out, int out_size) {
    const float* x    = (const float*)d_in[0];
    const float* adj  = (const float*)d_in[1];
    const float* Wk   = (const float*)d_in[2];
    const float* bk   = (const float*)d_in[3];
    const float* Wq   = (const float*)d_in[4];
    const float* bq   = (const float*)d_in[5];
    const float* Wv   = (const float*)d_in[6];
    const float* bv   = (const float*)d_in[7];
    const float* c1w  = (const float*)d_in[8];
    const float* c1b  = (const float*)d_in[9];
    const float* c2w  = (const float*)d_in[10];
    const float* c2b  = (const float*)d_in[11];
    const float* fw   = (const float*)d_in[12];
    const float* fb   = (const float*)d_in[13];
    const float* alpha= (const float*)d_in[14];
    float* out = (float*)d_out;

    k_sum_t<<<dim3(8, cN), 256>>>(x);
    k_att_kernel<<<dim3(2, cN), 256>>>(adj, Wk, bk, Wq, bq, c1w, c1b, c2w, c2b, fw, fb, alpha);
    k_vten<<<dim3(TV / CH, cN), 128>>>(x, Wv, bv);
    k_out<<<dim3(cO / 2, cN), 320>>>(out);
}